// round 12
// baseline (speedup 1.0000x reference)
#include <cuda_runtime.h>
#include <cstdint>
#include <cstddef>

// Problem: B=4, S=2048 -> TOK=8192 tokens, D=512, E=32, F=512
#define TOK   8192
#define DDIM  512
#define NEXP  32

// -------------------- device scratch --------------------
__device__ float g_gate[TOK * NEXP];   // softmax gates [t][e]
// Fragment-packed fp16 W for mma.m16n8k16:
// u32 chunks: [fb 4][dc 16][ks2 2][e 32] -> chunk of 1024 u32:
//   [wn 4][l 2][lane 32][r 4],  u32 = {lo=W[k][f], hi=W[k+1][f]}
//   k = dc*32 + ks2*16 + 2*(lane&3) + (r&1)*8
//   f = fb*128 + wn*32 + (l*2 + (r>>1))*8 + (lane>>2)
__device__ uint32_t g_wt2h[4 * 16 * 2 * 32 * 1024 + 2048];   // 16.8MB + 8KB pad

// -------------------- helpers --------------------
__device__ __forceinline__ uint32_t smem_u32(const void* p) {
    uint32_t a;
    asm("{ .reg .u64 t; cvta.to.shared.u64 t, %1; cvt.u32.u64 %0, t; }"
        : "=r"(a) : "l"(p));
    return a;
}
// pack two f32 -> f16x2 {lo, hi}  (first asm operand = hi half)
__device__ __forceinline__ uint32_t packh2(float lo, float hi) {
    uint32_t d;
    asm("cvt.rn.f16x2.f32 %0, %1, %2;" : "=r"(d) : "f"(hi), "f"(lo));
    return d;
}
__device__ __forceinline__ uint32_t hmul2(uint32_t a, uint32_t b) {
    uint32_t d;
    asm("mul.f16x2 %0, %1, %2;" : "=r"(d) : "r"(a), "r"(b));
    return d;
}
// fp32-accumulate form (gate kernel only)
__device__ __forceinline__ void mma_f16(float* c, uint32_t a0, uint32_t a1,
                                        uint32_t a2, uint32_t a3,
                                        uint32_t b0, uint32_t b1) {
    asm volatile(
        "mma.sync.aligned.m16n8k16.row.col.f32.f16.f16.f32 "
        "{%0,%1,%2,%3}, {%4,%5,%6,%7}, {%8,%9}, {%0,%1,%2,%3};"
        : "+f"(c[0]), "+f"(c[1]), "+f"(c[2]), "+f"(c[3])
        : "r"(a0), "r"(a1), "r"(a2), "r"(a3), "r"(b0), "r"(b1));
}
// fp16-accumulate form (main kernel — rt=8 hypothesis)
__device__ __forceinline__ void mma_f16h(uint32_t* c, uint32_t a0, uint32_t a1,
                                         uint32_t a2, uint32_t a3,
                                         uint32_t b0, uint32_t b1) {
    asm volatile(
        "mma.sync.aligned.m16n8k16.row.col.f16.f16.f16.f16 "
        "{%0,%1}, {%2,%3,%4,%5}, {%6,%7}, {%0,%1};"
        : "+r"(c[0]), "+r"(c[1])
        : "r"(a0), "r"(a1), "r"(a2), "r"(a3), "r"(b0), "r"(b1));
}

// ============ Kernel 1: fused prepass (W repack) + tensor-core gate ==========
// Blocks 0..511: prepass, e = bid & 31, dc = bid >> 5.
// Blocks 512..575: gate for tokens [ (bid-512)*128, +128 ).
#define PRE_SMEM (32 * 516 * 4)   // 66048 (covers gate's 12.5KB too)

__global__ void __launch_bounds__(256) prep_gate_kernel(
    const float* __restrict__ ew, const float* __restrict__ x,
    const float* __restrict__ gw, const float* __restrict__ gbias)
{
    extern __shared__ float ws[];
    int tid = threadIdx.x;
    int bid = blockIdx.x;

    if (bid < 512) {
        // ---------------- prepass: fragment-pack W to fp16 ----------------
        int e = bid & 31, dc = bid >> 5;
        const float4* src = reinterpret_cast<const float4*>(
            ew + ((size_t)e * DDIM + dc * 32) * DDIM);
        #pragma unroll
        for (int m = 0; m < 16; m++) {
            int v = tid + 256 * m;              // 4096 float4 = 32 rows x 128 f4
            int kk = v >> 7, fq = v & 127;
            float4 tv = src[v];
            *reinterpret_cast<float4*>(ws + kk * 516 + fq * 4) = tv;
        }
        __syncthreads();

        #pragma unroll
        for (int m = 0; m < 8; m++) {
            int v = tid + 256 * m;              // 2048 slots x uint4
            int lane = v & 31;
            int l    = (v >> 5) & 1;
            int wn   = (v >> 6) & 3;
            int ks2  = (v >> 8) & 1;
            int fb   = (v >> 9) & 3;
            int tig = lane & 3, gid = lane >> 2;
            uint32_t o[4];
            #pragma unroll
            for (int r = 0; r < 4; r++) {
                int k = ks2 * 16 + 2 * tig + (r & 1) * 8;   // within dc's 32
                int f = fb * 128 + wn * 32 + (l * 2 + (r >> 1)) * 8 + gid;
                o[r] = packh2(ws[k * 516 + f], ws[(k + 1) * 516 + f]);
            }
            size_t idx4 = ((((size_t)(fb * 16 + dc) * 2 + ks2) * 32 + e) * 256)
                        + wn * 64 + l * 32 + lane;
            reinterpret_cast<uint4*>(g_wt2h)[idx4] =
                make_uint4(o[0], o[1], o[2], o[3]);
        }
    } else {
        // ---------------- gate: fp16 MMA GEMM + softmax ----------------
        uint32_t* xsu  = reinterpret_cast<uint32_t*>(ws);          // [128][16] s20
        uint32_t* gwsu = reinterpret_cast<uint32_t*>(ws) + 128*20; // [16][32] s36
        int t0 = (bid - 512) * 128;
        int lane = tid & 31, w = tid >> 5;
        int tig = lane & 3, gid = lane >> 2;

        float acc[4][4];
        #pragma unroll
        for (int j = 0; j < 4; j++)
            #pragma unroll
            for (int q = 0; q < 4; q++) acc[j][q] = 0.f;

        #pragma unroll 1
        for (int dc = 0; dc < 16; dc++) {
            __syncthreads();
            #pragma unroll
            for (int m = 0; m < 4; m++) {
                int u = tid + 256 * m;          // 1024 float4
                int row = u >> 3, c4 = u & 7;
                float4 v = *reinterpret_cast<const float4*>(
                    x + (size_t)(t0 + row) * DDIM + dc * 32 + c4 * 4);
                xsu[row * 20 + c4 * 2]     = packh2(v.x, v.y);
                xsu[row * 20 + c4 * 2 + 1] = packh2(v.z, v.w);
            }
            {
                int kp = tid >> 4;              // 0..15
                int e2 = (tid & 15) * 2;        // 0..30
                float2 w0 = *reinterpret_cast<const float2*>(
                    gw + (size_t)(dc * 32 + 2 * kp) * NEXP + e2);
                float2 w1 = *reinterpret_cast<const float2*>(
                    gw + (size_t)(dc * 32 + 2 * kp + 1) * NEXP + e2);
                gwsu[kp * 36 + e2]     = packh2(w0.x, w1.x);
                gwsu[kp * 36 + e2 + 1] = packh2(w0.y, w1.y);
            }
            __syncthreads();

            #pragma unroll
            for (int kq = 0; kq < 2; kq++) {
                int kpb = kq * 8 + tig;
                uint32_t a0 = xsu[(w * 16 + gid) * 20 + kpb];
                uint32_t a1 = xsu[(w * 16 + gid + 8) * 20 + kpb];
                uint32_t a2 = xsu[(w * 16 + gid) * 20 + kpb + 4];
                uint32_t a3 = xsu[(w * 16 + gid + 8) * 20 + kpb + 4];
                #pragma unroll
                for (int j = 0; j < 4; j++) {
                    uint32_t b0 = gwsu[kpb * 36 + j * 8 + gid];
                    uint32_t b1 = gwsu[(kpb + 4) * 36 + j * 8 + gid];
                    mma_f16(acc[j], a0, a1, a2, a3, b0, b1);
                }
            }
        }

        // ---- bias + dual softmax (rows r0 and r0+8) + store ----
        float lr0[8], lr1[8];
        #pragma unroll
        for (int j = 0; j < 4; j++) {
            int c0 = j * 8 + tig * 2;
            float b0 = __ldg(gbias + c0), b1 = __ldg(gbias + c0 + 1);
            lr0[j * 2]     = acc[j][0] + b0;
            lr0[j * 2 + 1] = acc[j][1] + b1;
            lr1[j * 2]     = acc[j][2] + b0;
            lr1[j * 2 + 1] = acc[j][3] + b1;
        }
        float m0 = lr0[0], m1 = lr1[0];
        #pragma unroll
        for (int q = 1; q < 8; q++) {
            m0 = fmaxf(m0, lr0[q]); m1 = fmaxf(m1, lr1[q]);
        }
        #pragma unroll
        for (int o = 1; o <= 2; o <<= 1) {
            m0 = fmaxf(m0, __shfl_xor_sync(0xFFFFFFFFu, m0, o));
            m1 = fmaxf(m1, __shfl_xor_sync(0xFFFFFFFFu, m1, o));
        }
        float s0 = 0.f, s1 = 0.f;
        #pragma unroll
        for (int q = 0; q < 8; q++) {
            lr0[q] = __expf(lr0[q] - m0); s0 += lr0[q];
            lr1[q] = __expf(lr1[q] - m1); s1 += lr1[q];
        }
        #pragma unroll
        for (int o = 1; o <= 2; o <<= 1) {
            s0 += __shfl_xor_sync(0xFFFFFFFFu, s0, o);
            s1 += __shfl_xor_sync(0xFFFFFFFFu, s1, o);
        }
        float i0 = 1.0f / s0, i1 = 1.0f / s1;
        int r0 = t0 + w * 16 + gid;
        #pragma unroll
        for (int j = 0; j < 4; j++) {
            int c0 = j * 8 + tig * 2;
            *reinterpret_cast<float2*>(g_gate + (size_t)r0 * NEXP + c0) =
                make_float2(lr0[j * 2] * i0, lr0[j * 2 + 1] * i0);
            *reinterpret_cast<float2*>(g_gate + (size_t)(r0 + 8) * NEXP + c0) =
                make_float2(lr1[j * 2] * i1, lr1[j * 2 + 1] * i1);
        }
    }
}

// ======================== Kernel 2: main fp16 HMMA GEMM ======================
// grid (4 fblk, 128 tblk) = 512 CTAs of 128 threads, occ 3.
// 4 warps as 2(M) x 2(N); warp tile 32M x 64N; CTA tile 64M x 128N.
// ACCUMULATOR EXPERIMENT: mma m16n8k16 with fp16 C/D (rt=8 on sm_103a legacy
// pipe vs rt=16 for fp32-acc — the R5..R11 ~50%-tensor wall). fp16 partial
// sums are flushed into fp32 master accumulators every 2 e-iters (L=2 run
// length -> predicted +5.9e-4 rel err, combined ~7.7e-4 < 1e-3).
// B: register double-buffer over the linear chunk stream (R10-proven).
#define MAIN_SMEM ((64 * 20 + 64 * 36) * 4)   // 14336

#define LDB4(b0, b1, b2, b3, p) do {                                   \
    (b0) = *reinterpret_cast<const uint4*>(p);                         \
    (b1) = *reinterpret_cast<const uint4*>((p) + 128);                 \
    (b2) = *reinterpret_cast<const uint4*>((p) + 256);                 \
    (b3) = *reinterpret_cast<const uint4*>((p) + 384);                 \
} while (0)

// fp16-accumulate MMA block for expert e
#define MMABLOCK_H(e, q0, q1, q2, q3) do {                             \
    _Pragma("unroll")                                                  \
    for (int i = 0; i < 2; i++) {                                      \
        uint32_t g0, g1;                                               \
        asm("ld.shared.b32 %0, [%1];" : "=r"(g0)                       \
            : "r"(gA + (uint32_t)(i * 16 * 144 + (e) * 4)));           \
        asm("ld.shared.b32 %0, [%1];" : "=r"(g1)                       \
            : "r"(gA + (uint32_t)(i * 16 * 144 + 8 * 144 + (e) * 4))); \
        uint32_t a0 = hmul2(g0, xh[i][0]);                             \
        uint32_t a1 = hmul2(g1, xh[i][1]);                             \
        uint32_t a2 = hmul2(g0, xh[i][2]);                             \
        uint32_t a3 = hmul2(g1, xh[i][3]);                             \
        mma_f16h(accH[i][0], a0, a1, a2, a3, (q0).x, (q0).y);          \
        mma_f16h(accH[i][1], a0, a1, a2, a3, (q0).z, (q0).w);          \
        mma_f16h(accH[i][2], a0, a1, a2, a3, (q1).x, (q1).y);          \
        mma_f16h(accH[i][3], a0, a1, a2, a3, (q1).z, (q1).w);          \
        mma_f16h(accH[i][4], a0, a1, a2, a3, (q2).x, (q2).y);          \
        mma_f16h(accH[i][5], a0, a1, a2, a3, (q2).z, (q2).w);          \
        mma_f16h(accH[i][6], a0, a1, a2, a3, (q3).x, (q3).y);          \
        mma_f16h(accH[i][7], a0, a1, a2, a3, (q3).z, (q3).w);          \
    }                                                                  \
} while (0)

// flush fp16 partial sums into fp32 masters, reset fp16 accs
#define FLUSH() do {                                                   \
    _Pragma("unroll")                                                  \
    for (int i = 0; i < 2; i++)                                        \
        _Pragma("unroll")                                              \
        for (int j = 0; j < 8; j++) {                                  \
            float f0, f1, f2, f3;                                      \
            asm("{\n\t.reg .f16 l, h;\n\t"                             \
                "mov.b32 {l, h}, %2;\n\t"                              \
                "cvt.f32.f16 %0, l;\n\t"                               \
                "cvt.f32.f16 %1, h;\n\t}"                              \
                : "=f"(f0), "=f"(f1) : "r"(accH[i][j][0]));            \
            asm("{\n\t.reg .f16 l, h;\n\t"                             \
                "mov.b32 {l, h}, %2;\n\t"                              \
                "cvt.f32.f16 %0, l;\n\t"                               \
                "cvt.f32.f16 %1, h;\n\t}"                              \
                : "=f"(f2), "=f"(f3) : "r"(accH[i][j][1]));            \
            accF[i][j][0] += f0; accF[i][j][1] += f1;                  \
            accF[i][j][2] += f2; accF[i][j][3] += f3;                  \
            accH[i][j][0] = 0u;  accH[i][j][1] = 0u;                   \
        }                                                              \
} while (0)

__global__ void __launch_bounds__(128, 3) moe_main_kernel(
    const float* __restrict__ x, float* __restrict__ out)
{
    extern __shared__ uint32_t smu[];
    uint32_t* xsu = smu;              // [64][20]
    uint32_t* ghu = smu + 64 * 20;    // [64][36]
    uint32_t xcA = smem_u32(xsu);
    uint32_t ghA_base = xcA + 64u * 20u * 4u;

    int tid = threadIdx.x, lane = tid & 31, wid = tid >> 5;
    int wm = wid >> 1;              // 0..1 -> 32 rows each
    int wn = wid & 1;               // 0..1 -> 64 cols each
    int fblk = blockIdx.x;
    int t0 = blockIdx.y * 64;
    int f0 = fblk * 128;
    int tig = lane & 3, gid = lane >> 2;

    // ---- stage gate tile as replicated fp16x2 {g,g} (64 rows) ----
    #pragma unroll
    for (int m = 0; m < 4; m++) {
        int u = tid + 128 * m;      // 512 float4
        int row = u >> 3, wq = u & 7;
        float4 v = *reinterpret_cast<const float4*>(
            g_gate + (size_t)(t0 + row) * NEXP + wq * 4);
        ghu[row * 36 + wq * 4 + 0] = packh2(v.x, v.x);
        ghu[row * 36 + wq * 4 + 1] = packh2(v.y, v.y);
        ghu[row * 36 + wq * 4 + 2] = packh2(v.z, v.z);
        ghu[row * 36 + wq * 4 + 3] = packh2(v.w, v.w);
    }

    // ---- B stream: linear chunk order [dc][ks2][e], 1024 chunks ----
    const uint32_t* pB = g_wt2h + (size_t)fblk * (16 * 2 * 32 * 1024)
                       + (wn * 128 + lane) * 4;
    uint4 bA0, bA1, bA2, bA3, bB0, bB1, bB2, bB3;
    LDB4(bA0, bA1, bA2, bA3, pB);   // chunk 0
    pB += 1024;

    uint32_t accH[2][8][2];         // fp16x2 partial sums
    float accF[2][8][4];            // fp32 masters
    #pragma unroll
    for (int i = 0; i < 2; i++)
        #pragma unroll
        for (int j = 0; j < 8; j++) {
            accH[i][j][0] = 0u; accH[i][j][1] = 0u;
            #pragma unroll
            for (int q = 0; q < 4; q++) accF[i][j][q] = 0.f;
        }

    uint32_t xh[2][4];
    uint32_t gA = ghA_base + (uint32_t)(wm * 32 + gid) * 144u;

    #pragma unroll 1
    for (int dc = 0; dc < 16; dc++) {
        __syncthreads();
        // stage x chunk as fp16x2 pairs (64 rows)
        #pragma unroll
        for (int m = 0; m < 4; m++) {
            int u = tid + 128 * m;      // 512 float4
            int row = u >> 3, c4 = u & 7;
            float4 v = *reinterpret_cast<const float4*>(
                x + (size_t)(t0 + row) * DDIM + dc * 32 + c4 * 4);
            xsu[row * 20 + c4 * 2]     = packh2(v.x, v.y);
            xsu[row * 20 + c4 * 2 + 1] = packh2(v.z, v.w);
        }
        __syncthreads();

        #pragma unroll 1
        for (int ks2 = 0; ks2 < 2; ks2++) {
            // hoisted x-fragment loads (conflict-free banks)
            #pragma unroll
            for (int i = 0; i < 2; i++) {
                uint32_t base = xcA
                    + ((uint32_t)(wm * 32 + 16 * i + gid) * 20u
                       + (uint32_t)(ks2 * 8 + tig)) * 4u;
                asm("ld.shared.b32 %0, [%1];" : "=r"(xh[i][0]) : "r"(base));
                asm("ld.shared.b32 %0, [%1];" : "=r"(xh[i][1]) : "r"(base + 8u*20u*4u));
                asm("ld.shared.b32 %0, [%1];" : "=r"(xh[i][2]) : "r"(base + 16u));
                asm("ld.shared.b32 %0, [%1];" : "=r"(xh[i][3]) : "r"(base + 8u*20u*4u + 16u));
            }

            #pragma unroll 1
            for (int ep = 0; ep < 16; ep++) {   // e = 2*ep, 2*ep+1; flush after
                int e = 2 * ep;
                // prefetch chunk for e+1 while consuming chunk e
                LDB4(bB0, bB1, bB2, bB3, pB);
                pB += 1024;
                MMABLOCK_H(e, bA0, bA1, bA2, bA3);
                // prefetch chunk for e+2 (crosses ks2/dc boundaries; final
                // 1-chunk overrun lands in the 8KB pad)
                LDB4(bA0, bA1, bA2, bA3, pB);
                pB += 1024;
                MMABLOCK_H(e + 1, bB0, bB1, bB2, bB3);
                FLUSH();
            }
        }
    }

    // ---- epilogue (accH are zero after final FLUSH) ----
    #pragma unroll
    for (int i = 0; i < 2; i++) {
        int row = t0 + wm * 32 + 16 * i + gid;
        #pragma unroll
        for (int j = 0; j < 8; j++) {
            int col = f0 + wn * 64 + 8 * j + 2 * tig;
            *reinterpret_cast<float2*>(out + (size_t)row * DDIM + col) =
                make_float2(accF[i][j][0], accF[i][j][1]);
            *reinterpret_cast<float2*>(out + (size_t)(row + 8) * DDIM + col) =
                make_float2(accF[i][j][2], accF[i][j][3]);
        }
    }
}

// ======================== launch ========================
extern "C" void kernel_launch(void* const* d_in, const int* in_sizes, int n_in,
                              void* d_out, int out_size) {
    const float* x  = (const float*)d_in[0];   // [8192, 512]
    const float* gw = (const float*)d_in[1];   // [512, 32]
    const float* gb = (const float*)d_in[2];   // [32]
    const float* ew = (const float*)d_in[3];   // [32, 512, 512]
    float* out = (float*)d_out;                // [8192, 512]

    cudaFuncSetAttribute(prep_gate_kernel,
                         cudaFuncAttributeMaxDynamicSharedMemorySize, PRE_SMEM);
    cudaFuncSetAttribute(moe_main_kernel,
                         cudaFuncAttributeMaxDynamicSharedMemorySize, MAIN_SMEM);

    prep_gate_kernel<<<576, 256, PRE_SMEM>>>(ew, x, gw, gb);

    dim3 grid(4, 128);
    moe_main_kernel<<<grid, 128, MAIN_SMEM>>>(x, out);
}

// round 13
// speedup vs baseline: 1.0804x; 1.0804x over previous
#include <cuda_runtime.h>
#include <cstdint>
#include <cstddef>

// Problem: B=4, S=2048 -> TOK=8192 tokens, D=512, E=32, F=512
#define TOK   8192
#define DDIM  512
#define NEXP  32

// -------------------- device scratch --------------------
__device__ float g_gate[TOK * NEXP];   // softmax gates [t][e]
// Fragment-packed fp16 W for mma.m16n8k16:
// u32 chunks: [fb 4][dc 16][ks2 2][e 32] -> chunk of 1024 u32:
//   [wn 4][l 2][lane 32][r 4],  u32 = {lo=W[k][f], hi=W[k+1][f]}
//   k = dc*32 + ks2*16 + 2*(lane&3) + (r&1)*8
//   f = fb*128 + wn*32 + (l*2 + (r>>1))*8 + (lane>>2)
__device__ uint32_t g_wt2h[4 * 16 * 2 * 32 * 1024 + 2048];   // 16.8MB + 8KB pad

// -------------------- helpers --------------------
__device__ __forceinline__ uint32_t smem_u32(const void* p) {
    uint32_t a;
    asm("{ .reg .u64 t; cvta.to.shared.u64 t, %1; cvt.u32.u64 %0, t; }"
        : "=r"(a) : "l"(p));
    return a;
}
// pack two f32 -> f16x2 {lo, hi}  (first asm operand = hi half)
__device__ __forceinline__ uint32_t packh2(float lo, float hi) {
    uint32_t d;
    asm("cvt.rn.f16x2.f32 %0, %1, %2;" : "=r"(d) : "f"(hi), "f"(lo));
    return d;
}
__device__ __forceinline__ uint32_t hmul2(uint32_t a, uint32_t b) {
    uint32_t d;
    asm("mul.f16x2 %0, %1, %2;" : "=r"(d) : "r"(a), "r"(b));
    return d;
}
// fp32-accumulate form (gate kernel only)
__device__ __forceinline__ void mma_f16(float* c, uint32_t a0, uint32_t a1,
                                        uint32_t a2, uint32_t a3,
                                        uint32_t b0, uint32_t b1) {
    asm volatile(
        "mma.sync.aligned.m16n8k16.row.col.f32.f16.f16.f32 "
        "{%0,%1,%2,%3}, {%4,%5,%6,%7}, {%8,%9}, {%0,%1,%2,%3};"
        : "+f"(c[0]), "+f"(c[1]), "+f"(c[2]), "+f"(c[3])
        : "r"(a0), "r"(a1), "r"(a2), "r"(a3), "r"(b0), "r"(b1));
}
// fp16-accumulate form (main kernel — rt=8, confirmed R12)
__device__ __forceinline__ void mma_f16h(uint32_t* c, uint32_t a0, uint32_t a1,
                                         uint32_t a2, uint32_t a3,
                                         uint32_t b0, uint32_t b1) {
    asm volatile(
        "mma.sync.aligned.m16n8k16.row.col.f16.f16.f16.f16 "
        "{%0,%1}, {%2,%3,%4,%5}, {%6,%7}, {%0,%1};"
        : "+r"(c[0]), "+r"(c[1])
        : "r"(a0), "r"(a1), "r"(a2), "r"(a3), "r"(b0), "r"(b1));
}

// ============ Kernel 1: fused prepass (W repack) + tensor-core gate ==========
#define PRE_SMEM (32 * 516 * 4)   // 66048

__global__ void __launch_bounds__(256) prep_gate_kernel(
    const float* __restrict__ ew, const float* __restrict__ x,
    const float* __restrict__ gw, const float* __restrict__ gbias)
{
    extern __shared__ float ws[];
    int tid = threadIdx.x;
    int bid = blockIdx.x;

    if (bid < 512) {
        int e = bid & 31, dc = bid >> 5;
        const float4* src = reinterpret_cast<const float4*>(
            ew + ((size_t)e * DDIM + dc * 32) * DDIM);
        #pragma unroll
        for (int m = 0; m < 16; m++) {
            int v = tid + 256 * m;
            int kk = v >> 7, fq = v & 127;
            float4 tv = src[v];
            *reinterpret_cast<float4*>(ws + kk * 516 + fq * 4) = tv;
        }
        __syncthreads();

        #pragma unroll
        for (int m = 0; m < 8; m++) {
            int v = tid + 256 * m;
            int lane = v & 31;
            int l    = (v >> 5) & 1;
            int wn   = (v >> 6) & 3;
            int ks2  = (v >> 8) & 1;
            int fb   = (v >> 9) & 3;
            int tig = lane & 3, gid = lane >> 2;
            uint32_t o[4];
            #pragma unroll
            for (int r = 0; r < 4; r++) {
                int k = ks2 * 16 + 2 * tig + (r & 1) * 8;
                int f = fb * 128 + wn * 32 + (l * 2 + (r >> 1)) * 8 + gid;
                o[r] = packh2(ws[k * 516 + f], ws[(k + 1) * 516 + f]);
            }
            size_t idx4 = ((((size_t)(fb * 16 + dc) * 2 + ks2) * 32 + e) * 256)
                        + wn * 64 + l * 32 + lane;
            reinterpret_cast<uint4*>(g_wt2h)[idx4] =
                make_uint4(o[0], o[1], o[2], o[3]);
        }
    } else {
        uint32_t* xsu  = reinterpret_cast<uint32_t*>(ws);
        uint32_t* gwsu = reinterpret_cast<uint32_t*>(ws) + 128*20;
        int t0 = (bid - 512) * 128;
        int lane = tid & 31, w = tid >> 5;
        int tig = lane & 3, gid = lane >> 2;

        float acc[4][4];
        #pragma unroll
        for (int j = 0; j < 4; j++)
            #pragma unroll
            for (int q = 0; q < 4; q++) acc[j][q] = 0.f;

        #pragma unroll 1
        for (int dc = 0; dc < 16; dc++) {
            __syncthreads();
            #pragma unroll
            for (int m = 0; m < 4; m++) {
                int u = tid + 256 * m;
                int row = u >> 3, c4 = u & 7;
                float4 v = *reinterpret_cast<const float4*>(
                    x + (size_t)(t0 + row) * DDIM + dc * 32 + c4 * 4);
                xsu[row * 20 + c4 * 2]     = packh2(v.x, v.y);
                xsu[row * 20 + c4 * 2 + 1] = packh2(v.z, v.w);
            }
            {
                int kp = tid >> 4;
                int e2 = (tid & 15) * 2;
                float2 w0 = *reinterpret_cast<const float2*>(
                    gw + (size_t)(dc * 32 + 2 * kp) * NEXP + e2);
                float2 w1 = *reinterpret_cast<const float2*>(
                    gw + (size_t)(dc * 32 + 2 * kp + 1) * NEXP + e2);
                gwsu[kp * 36 + e2]     = packh2(w0.x, w1.x);
                gwsu[kp * 36 + e2 + 1] = packh2(w0.y, w1.y);
            }
            __syncthreads();

            #pragma unroll
            for (int kq = 0; kq < 2; kq++) {
                int kpb = kq * 8 + tig;
                uint32_t a0 = xsu[(w * 16 + gid) * 20 + kpb];
                uint32_t a1 = xsu[(w * 16 + gid + 8) * 20 + kpb];
                uint32_t a2 = xsu[(w * 16 + gid) * 20 + kpb + 4];
                uint32_t a3 = xsu[(w * 16 + gid + 8) * 20 + kpb + 4];
                #pragma unroll
                for (int j = 0; j < 4; j++) {
                    uint32_t b0 = gwsu[kpb * 36 + j * 8 + gid];
                    uint32_t b1 = gwsu[(kpb + 4) * 36 + j * 8 + gid];
                    mma_f16(acc[j], a0, a1, a2, a3, b0, b1);
                }
            }
        }

        float lr0[8], lr1[8];
        #pragma unroll
        for (int j = 0; j < 4; j++) {
            int c0 = j * 8 + tig * 2;
            float b0 = __ldg(gbias + c0), b1 = __ldg(gbias + c0 + 1);
            lr0[j * 2]     = acc[j][0] + b0;
            lr0[j * 2 + 1] = acc[j][1] + b1;
            lr1[j * 2]     = acc[j][2] + b0;
            lr1[j * 2 + 1] = acc[j][3] + b1;
        }
        float m0 = lr0[0], m1 = lr1[0];
        #pragma unroll
        for (int q = 1; q < 8; q++) {
            m0 = fmaxf(m0, lr0[q]); m1 = fmaxf(m1, lr1[q]);
        }
        #pragma unroll
        for (int o = 1; o <= 2; o <<= 1) {
            m0 = fmaxf(m0, __shfl_xor_sync(0xFFFFFFFFu, m0, o));
            m1 = fmaxf(m1, __shfl_xor_sync(0xFFFFFFFFu, m1, o));
        }
        float s0 = 0.f, s1 = 0.f;
        #pragma unroll
        for (int q = 0; q < 8; q++) {
            lr0[q] = __expf(lr0[q] - m0); s0 += lr0[q];
            lr1[q] = __expf(lr1[q] - m1); s1 += lr1[q];
        }
        #pragma unroll
        for (int o = 1; o <= 2; o <<= 1) {
            s0 += __shfl_xor_sync(0xFFFFFFFFu, s0, o);
            s1 += __shfl_xor_sync(0xFFFFFFFFu, s1, o);
        }
        float i0 = 1.0f / s0, i1 = 1.0f / s1;
        int r0 = t0 + w * 16 + gid;
        #pragma unroll
        for (int j = 0; j < 4; j++) {
            int c0 = j * 8 + tig * 2;
            *reinterpret_cast<float2*>(g_gate + (size_t)r0 * NEXP + c0) =
                make_float2(lr0[j * 2] * i0, lr0[j * 2 + 1] * i0);
            *reinterpret_cast<float2*>(g_gate + (size_t)(r0 + 8) * NEXP + c0) =
                make_float2(lr1[j * 2] * i1, lr1[j * 2 + 1] * i1);
        }
    }
}

// ======================== Kernel 2: main fp16 HMMA GEMM ======================
// fp16-accumulate MMA (rt=8) with flush period L=8 (128 flushes vs R12's 512).
// Predicted error: 2.55e-4 (measured @L=2) * sqrt(4) = 5.1e-4 -> combined
// ~7.1e-4. B: register double-buffer (bc/bn alternation, correct ordering).
#define MAIN_SMEM ((64 * 20 + 64 * 36) * 4)   // 14336

#define LDB4(b0, b1, b2, b3, p) do {                                   \
    (b0) = *reinterpret_cast<const uint4*>(p);                         \
    (b1) = *reinterpret_cast<const uint4*>((p) + 128);                 \
    (b2) = *reinterpret_cast<const uint4*>((p) + 256);                 \
    (b3) = *reinterpret_cast<const uint4*>((p) + 384);                 \
} while (0)

#define MMABLOCK_H(e, q0, q1, q2, q3) do {                             \
    _Pragma("unroll")                                                  \
    for (int i = 0; i < 2; i++) {                                      \
        uint32_t g0, g1;                                               \
        asm("ld.shared.b32 %0, [%1];" : "=r"(g0)                       \
            : "r"(gA + (uint32_t)(i * 16 * 144 + (e) * 4)));           \
        asm("ld.shared.b32 %0, [%1];" : "=r"(g1)                       \
            : "r"(gA + (uint32_t)(i * 16 * 144 + 8 * 144 + (e) * 4))); \
        uint32_t a0 = hmul2(g0, xh[i][0]);                             \
        uint32_t a1 = hmul2(g1, xh[i][1]);                             \
        uint32_t a2 = hmul2(g0, xh[i][2]);                             \
        uint32_t a3 = hmul2(g1, xh[i][3]);                             \
        mma_f16h(accH[i][0], a0, a1, a2, a3, (q0).x, (q0).y);          \
        mma_f16h(accH[i][1], a0, a1, a2, a3, (q0).z, (q0).w);          \
        mma_f16h(accH[i][2], a0, a1, a2, a3, (q1).x, (q1).y);          \
        mma_f16h(accH[i][3], a0, a1, a2, a3, (q1).z, (q1).w);          \
        mma_f16h(accH[i][4], a0, a1, a2, a3, (q2).x, (q2).y);          \
        mma_f16h(accH[i][5], a0, a1, a2, a3, (q2).z, (q2).w);          \
        mma_f16h(accH[i][6], a0, a1, a2, a3, (q3).x, (q3).y);          \
        mma_f16h(accH[i][7], a0, a1, a2, a3, (q3).z, (q3).w);          \
    }                                                                  \
} while (0)

// even step: fetch into bn*, consume bc*; odd step: fetch into bc*, consume bn*
#define STEP_EVEN(e) do {                                              \
    LDB4(bn0, bn1, bn2, bn3, pB); pB += 1024;                          \
    MMABLOCK_H((e), bc0, bc1, bc2, bc3);                               \
} while (0)
#define STEP_ODD(e) do {                                               \
    LDB4(bc0, bc1, bc2, bc3, pB); pB += 1024;                          \
    MMABLOCK_H((e), bn0, bn1, bn2, bn3);                               \
} while (0)

#define FLUSH() do {                                                   \
    _Pragma("unroll")                                                  \
    for (int i = 0; i < 2; i++)                                        \
        _Pragma("unroll")                                              \
        for (int j = 0; j < 8; j++) {                                  \
            float f0, f1, f2, f3;                                      \
            asm("{\n\t.reg .f16 l, h;\n\t"                             \
                "mov.b32 {l, h}, %2;\n\t"                              \
                "cvt.f32.f16 %0, l;\n\t"                               \
                "cvt.f32.f16 %1, h;\n\t}"                              \
                : "=f"(f0), "=f"(f1) : "r"(accH[i][j][0]));            \
            asm("{\n\t.reg .f16 l, h;\n\t"                             \
                "mov.b32 {l, h}, %2;\n\t"                              \
                "cvt.f32.f16 %0, l;\n\t"                               \
                "cvt.f32.f16 %1, h;\n\t}"                              \
                : "=f"(f2), "=f"(f3) : "r"(accH[i][j][1]));            \
            accF[i][j][0] += f0; accF[i][j][1] += f1;                  \
            accF[i][j][2] += f2; accF[i][j][3] += f3;                  \
            accH[i][j][0] = 0u;  accH[i][j][1] = 0u;                   \
        }                                                              \
} while (0)

__global__ void __launch_bounds__(128, 3) moe_main_kernel(
    const float* __restrict__ x, float* __restrict__ out)
{
    extern __shared__ uint32_t smu[];
    uint32_t* xsu = smu;              // [64][20]
    uint32_t* ghu = smu + 64 * 20;    // [64][36]
    uint32_t xcA = smem_u32(xsu);
    uint32_t ghA_base = xcA + 64u * 20u * 4u;

    int tid = threadIdx.x, lane = tid & 31, wid = tid >> 5;
    int wm = wid >> 1;
    int wn = wid & 1;
    int fblk = blockIdx.x;
    int t0 = blockIdx.y * 64;
    int f0 = fblk * 128;
    int tig = lane & 3, gid = lane >> 2;

    #pragma unroll
    for (int m = 0; m < 4; m++) {
        int u = tid + 128 * m;
        int row = u >> 3, wq = u & 7;
        float4 v = *reinterpret_cast<const float4*>(
            g_gate + (size_t)(t0 + row) * NEXP + wq * 4);
        ghu[row * 36 + wq * 4 + 0] = packh2(v.x, v.x);
        ghu[row * 36 + wq * 4 + 1] = packh2(v.y, v.y);
        ghu[row * 36 + wq * 4 + 2] = packh2(v.z, v.z);
        ghu[row * 36 + wq * 4 + 3] = packh2(v.w, v.w);
    }

    const uint32_t* pB = g_wt2h + (size_t)fblk * (16 * 2 * 32 * 1024)
                       + (wn * 128 + lane) * 4;
    uint4 bc0, bc1, bc2, bc3, bn0, bn1, bn2, bn3;
    LDB4(bc0, bc1, bc2, bc3, pB);   // chunk 0
    pB += 1024;

    uint32_t accH[2][8][2];
    float accF[2][8][4];
    #pragma unroll
    for (int i = 0; i < 2; i++)
        #pragma unroll
        for (int j = 0; j < 8; j++) {
            accH[i][j][0] = 0u; accH[i][j][1] = 0u;
            #pragma unroll
            for (int q = 0; q < 4; q++) accF[i][j][q] = 0.f;
        }

    uint32_t xh[2][4];
    uint32_t gA = ghA_base + (uint32_t)(wm * 32 + gid) * 144u;

    #pragma unroll 1
    for (int dc = 0; dc < 16; dc++) {
        __syncthreads();
        #pragma unroll
        for (int m = 0; m < 4; m++) {
            int u = tid + 128 * m;
            int row = u >> 3, c4 = u & 7;
            float4 v = *reinterpret_cast<const float4*>(
                x + (size_t)(t0 + row) * DDIM + dc * 32 + c4 * 4);
            xsu[row * 20 + c4 * 2]     = packh2(v.x, v.y);
            xsu[row * 20 + c4 * 2 + 1] = packh2(v.z, v.w);
        }
        __syncthreads();

        #pragma unroll 1
        for (int ks2 = 0; ks2 < 2; ks2++) {
            #pragma unroll
            for (int i = 0; i < 2; i++) {
                uint32_t base = xcA
                    + ((uint32_t)(wm * 32 + 16 * i + gid) * 20u
                       + (uint32_t)(ks2 * 8 + tig)) * 4u;
                asm("ld.shared.b32 %0, [%1];" : "=r"(xh[i][0]) : "r"(base));
                asm("ld.shared.b32 %0, [%1];" : "=r"(xh[i][1]) : "r"(base + 8u*20u*4u));
                asm("ld.shared.b32 %0, [%1];" : "=r"(xh[i][2]) : "r"(base + 16u));
                asm("ld.shared.b32 %0, [%1];" : "=r"(xh[i][3]) : "r"(base + 8u*20u*4u + 16u));
            }

            // 32 experts = 4 octets; flush after each octet (L=8).
            // Final 1-chunk prefetch overrun lands in the 8KB pad.
            #pragma unroll 1
            for (int eq = 0; eq < 4; eq++) {
                int e = eq * 8;
                STEP_EVEN(e + 0);
                STEP_ODD (e + 1);
                STEP_EVEN(e + 2);
                STEP_ODD (e + 3);
                STEP_EVEN(e + 4);
                STEP_ODD (e + 5);
                STEP_EVEN(e + 6);
                STEP_ODD (e + 7);
                FLUSH();
            }
        }
    }

    #pragma unroll
    for (int i = 0; i < 2; i++) {
        int row = t0 + wm * 32 + 16 * i + gid;
        #pragma unroll
        for (int j = 0; j < 8; j++) {
            int col = f0 + wn * 64 + 8 * j + 2 * tig;
            *reinterpret_cast<float2*>(out + (size_t)row * DDIM + col) =
                make_float2(accF[i][j][0], accF[i][j][1]);
            *reinterpret_cast<float2*>(out + (size_t)(row + 8) * DDIM + col) =
                make_float2(accF[i][j][2], accF[i][j][3]);
        }
    }
}

// ======================== launch ========================
extern "C" void kernel_launch(void* const* d_in, const int* in_sizes, int n_in,
                              void* d_out, int out_size) {
    const float* x  = (const float*)d_in[0];   // [8192, 512]
    const float* gw = (const float*)d_in[1];   // [512, 32]
    const float* gb = (const float*)d_in[2];   // [32]
    const float* ew = (const float*)d_in[3];   // [32, 512, 512]
    float* out = (float*)d_out;                // [8192, 512]

    cudaFuncSetAttribute(prep_gate_kernel,
                         cudaFuncAttributeMaxDynamicSharedMemorySize, PRE_SMEM);
    cudaFuncSetAttribute(moe_main_kernel,
                         cudaFuncAttributeMaxDynamicSharedMemorySize, MAIN_SMEM);

    prep_gate_kernel<<<576, 256, PRE_SMEM>>>(ew, x, gw, gb);

    dim3 grid(4, 128);
    moe_main_kernel<<<grid, 128, MAIN_SMEM>>>(x, out);
}

// round 14
// speedup vs baseline: 1.3576x; 1.2566x over previous
#include <cuda_runtime.h>
#include <cstdint>
#include <cstddef>

// Problem: B=4, S=2048 -> TOK=8192 tokens, D=512, E=32, F=512
#define TOK   8192
#define DDIM  512
#define NEXP  32

// -------------------- device scratch --------------------
__device__ float g_gate[TOK * NEXP];   // softmax gates [t][e]
// Fragment-packed fp16 W for mma.m16n8k16:
// u32 chunks: [fb 4][dc 16][ks2 2][e 32] -> chunk of 1024 u32:
//   [wn 4][l 2][lane 32][r 4],  u32 = {lo=W[k][f], hi=W[k+1][f]}
//   k = dc*32 + ks2*16 + 2*(lane&3) + (r&1)*8
//   f = fb*128 + wn*32 + (l*2 + (r>>1))*8 + (lane>>2)
__device__ uint32_t g_wt2h[4 * 16 * 2 * 32 * 1024 + 2048];   // 16.8MB + 8KB pad

// -------------------- helpers --------------------
__device__ __forceinline__ uint32_t smem_u32(const void* p) {
    uint32_t a;
    asm("{ .reg .u64 t; cvta.to.shared.u64 t, %1; cvt.u32.u64 %0, t; }"
        : "=r"(a) : "l"(p));
    return a;
}
// pack two f32 -> f16x2 {lo, hi}  (first asm operand = hi half)
__device__ __forceinline__ uint32_t packh2(float lo, float hi) {
    uint32_t d;
    asm("cvt.rn.f16x2.f32 %0, %1, %2;" : "=r"(d) : "f"(hi), "f"(lo));
    return d;
}
__device__ __forceinline__ uint32_t hmul2(uint32_t a, uint32_t b) {
    uint32_t d;
    asm("mul.f16x2 %0, %1, %2;" : "=r"(d) : "r"(a), "r"(b));
    return d;
}
// fp32-accumulate MMA (reverted from fp16-acc: R13 showed identical pipe time)
__device__ __forceinline__ void mma_f16(float* c, uint32_t a0, uint32_t a1,
                                        uint32_t a2, uint32_t a3,
                                        uint32_t b0, uint32_t b1) {
    asm volatile(
        "mma.sync.aligned.m16n8k16.row.col.f32.f16.f16.f32 "
        "{%0,%1,%2,%3}, {%4,%5,%6,%7}, {%8,%9}, {%0,%1,%2,%3};"
        : "+f"(c[0]), "+f"(c[1]), "+f"(c[2]), "+f"(c[3])
        : "r"(a0), "r"(a1), "r"(a2), "r"(a3), "r"(b0), "r"(b1));
}

// ============ Kernel 1: fused prepass (W repack) + tensor-core gate ==========
#define PRE_SMEM (32 * 516 * 4)   // 66048

__global__ void __launch_bounds__(256) prep_gate_kernel(
    const float* __restrict__ ew, const float* __restrict__ x,
    const float* __restrict__ gw, const float* __restrict__ gbias)
{
    extern __shared__ float ws[];
    int tid = threadIdx.x;
    int bid = blockIdx.x;

    if (bid < 512) {
        int e = bid & 31, dc = bid >> 5;
        const float4* src = reinterpret_cast<const float4*>(
            ew + ((size_t)e * DDIM + dc * 32) * DDIM);
        #pragma unroll
        for (int m = 0; m < 16; m++) {
            int v = tid + 256 * m;
            int kk = v >> 7, fq = v & 127;
            float4 tv = src[v];
            *reinterpret_cast<float4*>(ws + kk * 516 + fq * 4) = tv;
        }
        __syncthreads();

        #pragma unroll
        for (int m = 0; m < 8; m++) {
            int v = tid + 256 * m;
            int lane = v & 31;
            int l    = (v >> 5) & 1;
            int wn   = (v >> 6) & 3;
            int ks2  = (v >> 8) & 1;
            int fb   = (v >> 9) & 3;
            int tig = lane & 3, gid = lane >> 2;
            uint32_t o[4];
            #pragma unroll
            for (int r = 0; r < 4; r++) {
                int k = ks2 * 16 + 2 * tig + (r & 1) * 8;
                int f = fb * 128 + wn * 32 + (l * 2 + (r >> 1)) * 8 + gid;
                o[r] = packh2(ws[k * 516 + f], ws[(k + 1) * 516 + f]);
            }
            size_t idx4 = ((((size_t)(fb * 16 + dc) * 2 + ks2) * 32 + e) * 256)
                        + wn * 64 + l * 32 + lane;
            reinterpret_cast<uint4*>(g_wt2h)[idx4] =
                make_uint4(o[0], o[1], o[2], o[3]);
        }
    } else {
        uint32_t* xsu  = reinterpret_cast<uint32_t*>(ws);
        uint32_t* gwsu = reinterpret_cast<uint32_t*>(ws) + 128*20;
        int t0 = (bid - 512) * 128;
        int lane = tid & 31, w = tid >> 5;
        int tig = lane & 3, gid = lane >> 2;

        float acc[4][4];
        #pragma unroll
        for (int j = 0; j < 4; j++)
            #pragma unroll
            for (int q = 0; q < 4; q++) acc[j][q] = 0.f;

        #pragma unroll 1
        for (int dc = 0; dc < 16; dc++) {
            __syncthreads();
            #pragma unroll
            for (int m = 0; m < 4; m++) {
                int u = tid + 256 * m;
                int row = u >> 3, c4 = u & 7;
                float4 v = *reinterpret_cast<const float4*>(
                    x + (size_t)(t0 + row) * DDIM + dc * 32 + c4 * 4);
                xsu[row * 20 + c4 * 2]     = packh2(v.x, v.y);
                xsu[row * 20 + c4 * 2 + 1] = packh2(v.z, v.w);
            }
            {
                int kp = tid >> 4;
                int e2 = (tid & 15) * 2;
                float2 w0 = *reinterpret_cast<const float2*>(
                    gw + (size_t)(dc * 32 + 2 * kp) * NEXP + e2);
                float2 w1 = *reinterpret_cast<const float2*>(
                    gw + (size_t)(dc * 32 + 2 * kp + 1) * NEXP + e2);
                gwsu[kp * 36 + e2]     = packh2(w0.x, w1.x);
                gwsu[kp * 36 + e2 + 1] = packh2(w0.y, w1.y);
            }
            __syncthreads();

            #pragma unroll
            for (int kq = 0; kq < 2; kq++) {
                int kpb = kq * 8 + tig;
                uint32_t a0 = xsu[(w * 16 + gid) * 20 + kpb];
                uint32_t a1 = xsu[(w * 16 + gid + 8) * 20 + kpb];
                uint32_t a2 = xsu[(w * 16 + gid) * 20 + kpb + 4];
                uint32_t a3 = xsu[(w * 16 + gid + 8) * 20 + kpb + 4];
                #pragma unroll
                for (int j = 0; j < 4; j++) {
                    uint32_t b0 = gwsu[kpb * 36 + j * 8 + gid];
                    uint32_t b1 = gwsu[(kpb + 4) * 36 + j * 8 + gid];
                    mma_f16(acc[j], a0, a1, a2, a3, b0, b1);
                }
            }
        }

        float lr0[8], lr1[8];
        #pragma unroll
        for (int j = 0; j < 4; j++) {
            int c0 = j * 8 + tig * 2;
            float b0 = __ldg(gbias + c0), b1 = __ldg(gbias + c0 + 1);
            lr0[j * 2]     = acc[j][0] + b0;
            lr0[j * 2 + 1] = acc[j][1] + b1;
            lr1[j * 2]     = acc[j][2] + b0;
            lr1[j * 2 + 1] = acc[j][3] + b1;
        }
        float m0 = lr0[0], m1 = lr1[0];
        #pragma unroll
        for (int q = 1; q < 8; q++) {
            m0 = fmaxf(m0, lr0[q]); m1 = fmaxf(m1, lr1[q]);
        }
        #pragma unroll
        for (int o = 1; o <= 2; o <<= 1) {
            m0 = fmaxf(m0, __shfl_xor_sync(0xFFFFFFFFu, m0, o));
            m1 = fmaxf(m1, __shfl_xor_sync(0xFFFFFFFFu, m1, o));
        }
        float s0 = 0.f, s1 = 0.f;
        #pragma unroll
        for (int q = 0; q < 8; q++) {
            lr0[q] = __expf(lr0[q] - m0); s0 += lr0[q];
            lr1[q] = __expf(lr1[q] - m1); s1 += lr1[q];
        }
        #pragma unroll
        for (int o = 1; o <= 2; o <<= 1) {
            s0 += __shfl_xor_sync(0xFFFFFFFFu, s0, o);
            s1 += __shfl_xor_sync(0xFFFFFFFFu, s1, o);
        }
        float i0 = 1.0f / s0, i1 = 1.0f / s1;
        int r0 = t0 + w * 16 + gid;
        #pragma unroll
        for (int j = 0; j < 4; j++) {
            int c0 = j * 8 + tig * 2;
            *reinterpret_cast<float2*>(g_gate + (size_t)r0 * NEXP + c0) =
                make_float2(lr0[j * 2] * i0, lr0[j * 2 + 1] * i0);
            *reinterpret_cast<float2*>(g_gate + (size_t)(r0 + 8) * NEXP + c0) =
                make_float2(lr1[j * 2] * i1, lr1[j * 2 + 1] * i1);
        }
    }
}

// ======================== Kernel 2: main fp16 HMMA GEMM ======================
// grid (4 fblk, 128 tblk) = 512 CTAs of 128 threads, occ 4 (~single wave).
// 4 warps as 2(M) x 2(N); warp tile 32M x 64N (R10's winning shape);
// CTA tile 64M x 128N. The 4 warps per SMSP now come from 4 INDEPENDENT CTAs
// -> one CTA's staging sync no longer stalls its SMSP peers.
// fp32-accumulate MMA (R13 disproved any fp16-acc rate advantage).
// B: register double-buffer, distance 1 (R10-proven). Gate loads: e-unroll-2
// with v2 pair loads (2 LDS.64 per 2 experts, latency amortized).
#define MAIN_SMEM ((64 * 20 + 64 * 36) * 4)   // 14336

#define LDB4(b0, b1, b2, b3, p) do {                                   \
    (b0) = *reinterpret_cast<const uint4*>(p);                         \
    (b1) = *reinterpret_cast<const uint4*>((p) + 128);                 \
    (b2) = *reinterpret_cast<const uint4*>((p) + 256);                 \
    (b3) = *reinterpret_cast<const uint4*>((p) + 384);                 \
} while (0)

// MMA block using pre-loaded gate registers gpe[i][half][u]
#define MMABLOCK_R(u, q0, q1, q2, q3) do {                             \
    _Pragma("unroll")                                                  \
    for (int i = 0; i < 2; i++) {                                      \
        uint32_t a0 = hmul2(gpe[i][0][u], xh[i][0]);                   \
        uint32_t a1 = hmul2(gpe[i][1][u], xh[i][1]);                   \
        uint32_t a2 = hmul2(gpe[i][0][u], xh[i][2]);                   \
        uint32_t a3 = hmul2(gpe[i][1][u], xh[i][3]);                   \
        mma_f16(acc[i][0], a0, a1, a2, a3, (q0).x, (q0).y);            \
        mma_f16(acc[i][1], a0, a1, a2, a3, (q0).z, (q0).w);            \
        mma_f16(acc[i][2], a0, a1, a2, a3, (q1).x, (q1).y);            \
        mma_f16(acc[i][3], a0, a1, a2, a3, (q1).z, (q1).w);            \
        mma_f16(acc[i][4], a0, a1, a2, a3, (q2).x, (q2).y);            \
        mma_f16(acc[i][5], a0, a1, a2, a3, (q2).z, (q2).w);            \
        mma_f16(acc[i][6], a0, a1, a2, a3, (q3).x, (q3).y);            \
        mma_f16(acc[i][7], a0, a1, a2, a3, (q3).z, (q3).w);            \
    }                                                                  \
} while (0)

__global__ void __launch_bounds__(128, 4) moe_main_kernel(
    const float* __restrict__ x, float* __restrict__ out)
{
    extern __shared__ uint32_t smu[];
    uint32_t* xsu = smu;              // [64][20]
    uint32_t* ghu = smu + 64 * 20;    // [64][36]
    uint32_t xcA = smem_u32(xsu);
    uint32_t ghA_base = xcA + 64u * 20u * 4u;

    int tid = threadIdx.x, lane = tid & 31, wid = tid >> 5;
    int wm = wid >> 1;              // 0..1 -> 32 rows each
    int wn = wid & 1;               // 0..1 -> 64 cols each
    int fblk = blockIdx.x;
    int t0 = blockIdx.y * 64;
    int f0 = fblk * 128;
    int tig = lane & 3, gid = lane >> 2;

    // ---- stage gate tile as replicated fp16x2 {g,g} (64 rows) ----
    #pragma unroll
    for (int m = 0; m < 4; m++) {
        int u = tid + 128 * m;      // 512 float4
        int row = u >> 3, wq = u & 7;
        float4 v = *reinterpret_cast<const float4*>(
            g_gate + (size_t)(t0 + row) * NEXP + wq * 4);
        ghu[row * 36 + wq * 4 + 0] = packh2(v.x, v.x);
        ghu[row * 36 + wq * 4 + 1] = packh2(v.y, v.y);
        ghu[row * 36 + wq * 4 + 2] = packh2(v.z, v.z);
        ghu[row * 36 + wq * 4 + 3] = packh2(v.w, v.w);
    }

    // ---- B stream: linear chunk order [dc][ks2][e], 1024 chunks ----
    const uint32_t* pB = g_wt2h + (size_t)fblk * (16 * 2 * 32 * 1024)
                       + (wn * 128 + lane) * 4;
    uint4 bc0, bc1, bc2, bc3, bn0, bn1, bn2, bn3;
    LDB4(bc0, bc1, bc2, bc3, pB);   // chunk 0
    pB += 1024;

    float acc[2][8][4];
    #pragma unroll
    for (int i = 0; i < 2; i++)
        #pragma unroll
        for (int j = 0; j < 8; j++)
            #pragma unroll
            for (int q = 0; q < 4; q++) acc[i][j][q] = 0.f;

    uint32_t xh[2][4];
    uint32_t gA = ghA_base + (uint32_t)(wm * 32 + gid) * 144u;

    #pragma unroll 1
    for (int dc = 0; dc < 16; dc++) {
        __syncthreads();
        // stage x chunk as fp16x2 pairs (64 rows)
        #pragma unroll
        for (int m = 0; m < 4; m++) {
            int u = tid + 128 * m;      // 512 float4
            int row = u >> 3, c4 = u & 7;
            float4 v = *reinterpret_cast<const float4*>(
                x + (size_t)(t0 + row) * DDIM + dc * 32 + c4 * 4);
            xsu[row * 20 + c4 * 2]     = packh2(v.x, v.y);
            xsu[row * 20 + c4 * 2 + 1] = packh2(v.z, v.w);
        }
        __syncthreads();

        #pragma unroll 1
        for (int ks2 = 0; ks2 < 2; ks2++) {
            // hoisted x-fragment loads (conflict-free banks)
            #pragma unroll
            for (int i = 0; i < 2; i++) {
                uint32_t base = xcA
                    + ((uint32_t)(wm * 32 + 16 * i + gid) * 20u
                       + (uint32_t)(ks2 * 8 + tig)) * 4u;
                asm("ld.shared.b32 %0, [%1];" : "=r"(xh[i][0]) : "r"(base));
                asm("ld.shared.b32 %0, [%1];" : "=r"(xh[i][1]) : "r"(base + 8u*20u*4u));
                asm("ld.shared.b32 %0, [%1];" : "=r"(xh[i][2]) : "r"(base + 16u));
                asm("ld.shared.b32 %0, [%1];" : "=r"(xh[i][3]) : "r"(base + 8u*20u*4u + 16u));
            }

            // e-unrolled x2: v2 gate pair loads + alternating B buffers.
            // Final 1-chunk prefetch overrun lands in the 8KB pad.
            #pragma unroll 1
            for (int ep = 0; ep < 16; ep++) {
                uint32_t gpe[2][2][2];   // [i][row-half][u]
                #pragma unroll
                for (int i = 0; i < 2; i++) {
                    asm("ld.shared.v2.b32 {%0,%1}, [%2];"
                        : "=r"(gpe[i][0][0]), "=r"(gpe[i][0][1])
                        : "r"(gA + (uint32_t)(i * 2304) + (uint32_t)(ep * 8)));
                    asm("ld.shared.v2.b32 {%0,%1}, [%2];"
                        : "=r"(gpe[i][1][0]), "=r"(gpe[i][1][1])
                        : "r"(gA + (uint32_t)(i * 2304 + 1152) + (uint32_t)(ep * 8)));
                }
                // e = 2*ep: fetch next into bn*, consume bc*
                LDB4(bn0, bn1, bn2, bn3, pB); pB += 1024;
                MMABLOCK_R(0, bc0, bc1, bc2, bc3);
                // e = 2*ep+1: fetch next into bc*, consume bn*
                LDB4(bc0, bc1, bc2, bc3, pB); pB += 1024;
                MMABLOCK_R(1, bn0, bn1, bn2, bn3);
            }
        }
    }

    // ---- epilogue ----
    #pragma unroll
    for (int i = 0; i < 2; i++) {
        int row = t0 + wm * 32 + 16 * i + gid;
        #pragma unroll
        for (int j = 0; j < 8; j++) {
            int col = f0 + wn * 64 + 8 * j + 2 * tig;
            *reinterpret_cast<float2*>(out + (size_t)row * DDIM + col) =
                make_float2(acc[i][j][0], acc[i][j][1]);
            *reinterpret_cast<float2*>(out + (size_t)(row + 8) * DDIM + col) =
                make_float2(acc[i][j][2], acc[i][j][3]);
        }
    }
}

// ======================== launch ========================
extern "C" void kernel_launch(void* const* d_in, const int* in_sizes, int n_in,
                              void* d_out, int out_size) {
    const float* x  = (const float*)d_in[0];   // [8192, 512]
    const float* gw = (const float*)d_in[1];   // [512, 32]
    const float* gb = (const float*)d_in[2];   // [32]
    const float* ew = (const float*)d_in[3];   // [32, 512, 512]
    float* out = (float*)d_out;                // [8192, 512]

    cudaFuncSetAttribute(prep_gate_kernel,
                         cudaFuncAttributeMaxDynamicSharedMemorySize, PRE_SMEM);
    cudaFuncSetAttribute(moe_main_kernel,
                         cudaFuncAttributeMaxDynamicSharedMemorySize, MAIN_SMEM);

    prep_gate_kernel<<<576, 256, PRE_SMEM>>>(ew, x, gw, gb);

    dim3 grid(4, 128);
    moe_main_kernel<<<grid, 128, MAIN_SMEM>>>(x, out);
}

// round 15
// speedup vs baseline: 1.5012x; 1.1058x over previous
#include <cuda_runtime.h>
#include <cstdint>
#include <cstddef>

// Problem: B=4, S=2048 -> TOK=8192 tokens, D=512, E=32, F=512
#define TOK   8192
#define DDIM  512
#define NEXP  32

// -------------------- device scratch --------------------
__device__ float g_gate[TOK * NEXP];   // softmax gates [t][e]
// Fragment-packed fp16 W for mma.m16n8k16:
// u32 chunks: [fb 4][dc 16][ks2 2][e 32] -> chunk of 1024 u32:
//   [wn 4][l 2][lane 32][r 4],  u32 = {lo=W[k][f], hi=W[k+1][f]}
//   k = dc*32 + ks2*16 + 2*(lane&3) + (r&1)*8
//   f = fb*128 + wn*32 + (l*2 + (r>>1))*8 + (lane>>2)
__device__ uint32_t g_wt2h[4 * 16 * 2 * 32 * 1024 + 2048];   // 16.8MB + 8KB pad

// -------------------- helpers --------------------
__device__ __forceinline__ uint32_t smem_u32(const void* p) {
    uint32_t a;
    asm("{ .reg .u64 t; cvta.to.shared.u64 t, %1; cvt.u32.u64 %0, t; }"
        : "=r"(a) : "l"(p));
    return a;
}
// pack two f32 -> f16x2 {lo, hi}  (first asm operand = hi half)
__device__ __forceinline__ uint32_t packh2(float lo, float hi) {
    uint32_t d;
    asm("cvt.rn.f16x2.f32 %0, %1, %2;" : "=r"(d) : "f"(hi), "f"(lo));
    return d;
}
__device__ __forceinline__ uint32_t hmul2(uint32_t a, uint32_t b) {
    uint32_t d;
    asm("mul.f16x2 %0, %1, %2;" : "=r"(d) : "r"(a), "r"(b));
    return d;
}
// fp32-accumulate MMA
__device__ __forceinline__ void mma_f16(float* c, uint32_t a0, uint32_t a1,
                                        uint32_t a2, uint32_t a3,
                                        uint32_t b0, uint32_t b1) {
    asm volatile(
        "mma.sync.aligned.m16n8k16.row.col.f32.f16.f16.f32 "
        "{%0,%1,%2,%3}, {%4,%5,%6,%7}, {%8,%9}, {%0,%1,%2,%3};"
        : "+f"(c[0]), "+f"(c[1]), "+f"(c[2]), "+f"(c[3])
        : "r"(a0), "r"(a1), "r"(a2), "r"(a3), "r"(b0), "r"(b1));
}

// ============ Kernel 1: fused prepass (W repack) + tensor-core gate ==========
#define PRE_SMEM (32 * 516 * 4)   // 66048

__global__ void __launch_bounds__(256) prep_gate_kernel(
    const float* __restrict__ ew, const float* __restrict__ x,
    const float* __restrict__ gw, const float* __restrict__ gbias)
{
    extern __shared__ float ws[];
    int tid = threadIdx.x;
    int bid = blockIdx.x;

    if (bid < 512) {
        int e = bid & 31, dc = bid >> 5;
        const float4* src = reinterpret_cast<const float4*>(
            ew + ((size_t)e * DDIM + dc * 32) * DDIM);
        #pragma unroll
        for (int m = 0; m < 16; m++) {
            int v = tid + 256 * m;
            int kk = v >> 7, fq = v & 127;
            float4 tv = src[v];
            *reinterpret_cast<float4*>(ws + kk * 516 + fq * 4) = tv;
        }
        __syncthreads();

        #pragma unroll
        for (int m = 0; m < 8; m++) {
            int v = tid + 256 * m;
            int lane = v & 31;
            int l    = (v >> 5) & 1;
            int wn   = (v >> 6) & 3;
            int ks2  = (v >> 8) & 1;
            int fb   = (v >> 9) & 3;
            int tig = lane & 3, gid = lane >> 2;
            uint32_t o[4];
            #pragma unroll
            for (int r = 0; r < 4; r++) {
                int k = ks2 * 16 + 2 * tig + (r & 1) * 8;
                int f = fb * 128 + wn * 32 + (l * 2 + (r >> 1)) * 8 + gid;
                o[r] = packh2(ws[k * 516 + f], ws[(k + 1) * 516 + f]);
            }
            size_t idx4 = ((((size_t)(fb * 16 + dc) * 2 + ks2) * 32 + e) * 256)
                        + wn * 64 + l * 32 + lane;
            reinterpret_cast<uint4*>(g_wt2h)[idx4] =
                make_uint4(o[0], o[1], o[2], o[3]);
        }
    } else {
        uint32_t* xsu  = reinterpret_cast<uint32_t*>(ws);
        uint32_t* gwsu = reinterpret_cast<uint32_t*>(ws) + 128*20;
        int t0 = (bid - 512) * 128;
        int lane = tid & 31, w = tid >> 5;
        int tig = lane & 3, gid = lane >> 2;

        float acc[4][4];
        #pragma unroll
        for (int j = 0; j < 4; j++)
            #pragma unroll
            for (int q = 0; q < 4; q++) acc[j][q] = 0.f;

        #pragma unroll 1
        for (int dc = 0; dc < 16; dc++) {
            __syncthreads();
            #pragma unroll
            for (int m = 0; m < 4; m++) {
                int u = tid + 256 * m;
                int row = u >> 3, c4 = u & 7;
                float4 v = *reinterpret_cast<const float4*>(
                    x + (size_t)(t0 + row) * DDIM + dc * 32 + c4 * 4);
                xsu[row * 20 + c4 * 2]     = packh2(v.x, v.y);
                xsu[row * 20 + c4 * 2 + 1] = packh2(v.z, v.w);
            }
            {
                int kp = tid >> 4;
                int e2 = (tid & 15) * 2;
                float2 w0 = *reinterpret_cast<const float2*>(
                    gw + (size_t)(dc * 32 + 2 * kp) * NEXP + e2);
                float2 w1 = *reinterpret_cast<const float2*>(
                    gw + (size_t)(dc * 32 + 2 * kp + 1) * NEXP + e2);
                gwsu[kp * 36 + e2]     = packh2(w0.x, w1.x);
                gwsu[kp * 36 + e2 + 1] = packh2(w0.y, w1.y);
            }
            __syncthreads();

            #pragma unroll
            for (int kq = 0; kq < 2; kq++) {
                int kpb = kq * 8 + tig;
                uint32_t a0 = xsu[(w * 16 + gid) * 20 + kpb];
                uint32_t a1 = xsu[(w * 16 + gid + 8) * 20 + kpb];
                uint32_t a2 = xsu[(w * 16 + gid) * 20 + kpb + 4];
                uint32_t a3 = xsu[(w * 16 + gid + 8) * 20 + kpb + 4];
                #pragma unroll
                for (int j = 0; j < 4; j++) {
                    uint32_t b0 = gwsu[kpb * 36 + j * 8 + gid];
                    uint32_t b1 = gwsu[(kpb + 4) * 36 + j * 8 + gid];
                    mma_f16(acc[j], a0, a1, a2, a3, b0, b1);
                }
            }
        }

        float lr0[8], lr1[8];
        #pragma unroll
        for (int j = 0; j < 4; j++) {
            int c0 = j * 8 + tig * 2;
            float b0 = __ldg(gbias + c0), b1 = __ldg(gbias + c0 + 1);
            lr0[j * 2]     = acc[j][0] + b0;
            lr0[j * 2 + 1] = acc[j][1] + b1;
            lr1[j * 2]     = acc[j][2] + b0;
            lr1[j * 2 + 1] = acc[j][3] + b1;
        }
        float m0 = lr0[0], m1 = lr1[0];
        #pragma unroll
        for (int q = 1; q < 8; q++) {
            m0 = fmaxf(m0, lr0[q]); m1 = fmaxf(m1, lr1[q]);
        }
        #pragma unroll
        for (int o = 1; o <= 2; o <<= 1) {
            m0 = fmaxf(m0, __shfl_xor_sync(0xFFFFFFFFu, m0, o));
            m1 = fmaxf(m1, __shfl_xor_sync(0xFFFFFFFFu, m1, o));
        }
        float s0 = 0.f, s1 = 0.f;
        #pragma unroll
        for (int q = 0; q < 8; q++) {
            lr0[q] = __expf(lr0[q] - m0); s0 += lr0[q];
            lr1[q] = __expf(lr1[q] - m1); s1 += lr1[q];
        }
        #pragma unroll
        for (int o = 1; o <= 2; o <<= 1) {
            s0 += __shfl_xor_sync(0xFFFFFFFFu, s0, o);
            s1 += __shfl_xor_sync(0xFFFFFFFFu, s1, o);
        }
        float i0 = 1.0f / s0, i1 = 1.0f / s1;
        int r0 = t0 + w * 16 + gid;
        #pragma unroll
        for (int j = 0; j < 4; j++) {
            int c0 = j * 8 + tig * 2;
            *reinterpret_cast<float2*>(g_gate + (size_t)r0 * NEXP + c0) =
                make_float2(lr0[j * 2] * i0, lr0[j * 2 + 1] * i0);
            *reinterpret_cast<float2*>(g_gate + (size_t)(r0 + 8) * NEXP + c0) =
                make_float2(lr1[j * 2] * i1, lr1[j * 2 + 1] * i1);
        }
    }
}

// ======================== Kernel 2: main fp16 HMMA GEMM ======================
// grid (4 fblk, 64 tblk) = 256 CTAs of 128 threads, occ 2.
// 4 warps as 2(M) x 2(N); WARP TILE 64M x 64N (32 MMA per e-iter) — doubles
// the MMA run length per B-load (B regs reused x4 across 4 m-fragments), so
// per-warp pipe demand 2x256cyc vs iter ~460cyc -> tensor pipe saturates.
// fp32-accumulate; B register double-buffer distance-1 (proven path).
#define MAIN_SMEM ((128 * 20 + 128 * 36) * 4)   // 28672

#define LDB4(b0, b1, b2, b3, p) do {                                   \
    (b0) = *reinterpret_cast<const uint4*>(p);                         \
    (b1) = *reinterpret_cast<const uint4*>((p) + 128);                 \
    (b2) = *reinterpret_cast<const uint4*>((p) + 256);                 \
    (b3) = *reinterpret_cast<const uint4*>((p) + 384);                 \
} while (0)

// 32-MMA block (4 m-fragments x 8 n-tiles) using pre-loaded gates gpe[i][h][u]
#define MMABLOCK_R(u, q0, q1, q2, q3) do {                             \
    _Pragma("unroll")                                                  \
    for (int i = 0; i < 4; i++) {                                      \
        uint32_t a0 = hmul2(gpe[i][0][u], xh[i][0]);                   \
        uint32_t a1 = hmul2(gpe[i][1][u], xh[i][1]);                   \
        uint32_t a2 = hmul2(gpe[i][0][u], xh[i][2]);                   \
        uint32_t a3 = hmul2(gpe[i][1][u], xh[i][3]);                   \
        mma_f16(acc[i][0], a0, a1, a2, a3, (q0).x, (q0).y);            \
        mma_f16(acc[i][1], a0, a1, a2, a3, (q0).z, (q0).w);            \
        mma_f16(acc[i][2], a0, a1, a2, a3, (q1).x, (q1).y);            \
        mma_f16(acc[i][3], a0, a1, a2, a3, (q1).z, (q1).w);            \
        mma_f16(acc[i][4], a0, a1, a2, a3, (q2).x, (q2).y);            \
        mma_f16(acc[i][5], a0, a1, a2, a3, (q2).z, (q2).w);            \
        mma_f16(acc[i][6], a0, a1, a2, a3, (q3).x, (q3).y);            \
        mma_f16(acc[i][7], a0, a1, a2, a3, (q3).z, (q3).w);            \
    }                                                                  \
} while (0)

__global__ void __launch_bounds__(128, 2) moe_main_kernel(
    const float* __restrict__ x, float* __restrict__ out)
{
    extern __shared__ uint32_t smu[];
    uint32_t* xsu = smu;               // [128][20]
    uint32_t* ghu = smu + 128 * 20;    // [128][36]
    uint32_t xcA = smem_u32(xsu);
    uint32_t ghA_base = xcA + 128u * 20u * 4u;

    int tid = threadIdx.x, lane = tid & 31, wid = tid >> 5;
    int wm = wid >> 1;              // 0..1 -> 64 rows each
    int wn = wid & 1;               // 0..1 -> 64 cols each
    int fblk = blockIdx.x;
    int t0 = blockIdx.y * 128;
    int f0 = fblk * 128;
    int tig = lane & 3, gid = lane >> 2;

    // ---- stage gate tile as replicated fp16x2 {g,g} (128 rows) ----
    #pragma unroll
    for (int m = 0; m < 8; m++) {
        int u = tid + 128 * m;      // 1024 float4
        int row = u >> 3, wq = u & 7;
        float4 v = *reinterpret_cast<const float4*>(
            g_gate + (size_t)(t0 + row) * NEXP + wq * 4);
        ghu[row * 36 + wq * 4 + 0] = packh2(v.x, v.x);
        ghu[row * 36 + wq * 4 + 1] = packh2(v.y, v.y);
        ghu[row * 36 + wq * 4 + 2] = packh2(v.z, v.z);
        ghu[row * 36 + wq * 4 + 3] = packh2(v.w, v.w);
    }

    // ---- B stream: linear chunk order [dc][ks2][e], 1024 chunks ----
    const uint32_t* pB = g_wt2h + (size_t)fblk * (16 * 2 * 32 * 1024)
                       + (wn * 128 + lane) * 4;
    uint4 bc0, bc1, bc2, bc3, bn0, bn1, bn2, bn3;
    LDB4(bc0, bc1, bc2, bc3, pB);   // chunk 0
    pB += 1024;

    float acc[4][8][4];
    #pragma unroll
    for (int i = 0; i < 4; i++)
        #pragma unroll
        for (int j = 0; j < 8; j++)
            #pragma unroll
            for (int q = 0; q < 4; q++) acc[i][j][q] = 0.f;

    uint32_t xh[4][4];
    uint32_t gA = ghA_base + (uint32_t)(wm * 64 + gid) * 144u;

    #pragma unroll 1
    for (int dc = 0; dc < 16; dc++) {
        __syncthreads();
        // stage x chunk as fp16x2 pairs (128 rows)
        #pragma unroll
        for (int m = 0; m < 8; m++) {
            int u = tid + 128 * m;      // 1024 float4
            int row = u >> 3, c4 = u & 7;
            float4 v = *reinterpret_cast<const float4*>(
                x + (size_t)(t0 + row) * DDIM + dc * 32 + c4 * 4);
            xsu[row * 20 + c4 * 2]     = packh2(v.x, v.y);
            xsu[row * 20 + c4 * 2 + 1] = packh2(v.z, v.w);
        }
        __syncthreads();

        #pragma unroll 1
        for (int ks2 = 0; ks2 < 2; ks2++) {
            // hoisted x-fragment loads (conflict-free banks)
            #pragma unroll
            for (int i = 0; i < 4; i++) {
                uint32_t base = xcA
                    + ((uint32_t)(wm * 64 + 16 * i + gid) * 20u
                       + (uint32_t)(ks2 * 8 + tig)) * 4u;
                asm("ld.shared.b32 %0, [%1];" : "=r"(xh[i][0]) : "r"(base));
                asm("ld.shared.b32 %0, [%1];" : "=r"(xh[i][1]) : "r"(base + 8u*20u*4u));
                asm("ld.shared.b32 %0, [%1];" : "=r"(xh[i][2]) : "r"(base + 16u));
                asm("ld.shared.b32 %0, [%1];" : "=r"(xh[i][3]) : "r"(base + 8u*20u*4u + 16u));
            }

            // e-unrolled x2; final 1-chunk prefetch overrun lands in the pad
            #pragma unroll 1
            for (int ep = 0; ep < 16; ep++) {
                uint32_t gpe[4][2][2];   // [i][row-half][u]
                #pragma unroll
                for (int i = 0; i < 4; i++) {
                    asm("ld.shared.v2.b32 {%0,%1}, [%2];"
                        : "=r"(gpe[i][0][0]), "=r"(gpe[i][0][1])
                        : "r"(gA + (uint32_t)(i * 2304) + (uint32_t)(ep * 8)));
                    asm("ld.shared.v2.b32 {%0,%1}, [%2];"
                        : "=r"(gpe[i][1][0]), "=r"(gpe[i][1][1])
                        : "r"(gA + (uint32_t)(i * 2304 + 1152) + (uint32_t)(ep * 8)));
                }
                // e = 2*ep: fetch next into bn*, consume bc*
                LDB4(bn0, bn1, bn2, bn3, pB); pB += 1024;
                MMABLOCK_R(0, bc0, bc1, bc2, bc3);
                // e = 2*ep+1: fetch next into bc*, consume bn*
                LDB4(bc0, bc1, bc2, bc3, pB); pB += 1024;
                MMABLOCK_R(1, bn0, bn1, bn2, bn3);
            }
        }
    }

    // ---- epilogue ----
    #pragma unroll
    for (int i = 0; i < 4; i++) {
        int row = t0 + wm * 64 + 16 * i + gid;
        #pragma unroll
        for (int j = 0; j < 8; j++) {
            int col = f0 + wn * 64 + 8 * j + 2 * tig;
            *reinterpret_cast<float2*>(out + (size_t)row * DDIM + col) =
                make_float2(acc[i][j][0], acc[i][j][1]);
            *reinterpret_cast<float2*>(out + (size_t)(row + 8) * DDIM + col) =
                make_float2(acc[i][j][2], acc[i][j][3]);
        }
    }
}

// ======================== launch ========================
extern "C" void kernel_launch(void* const* d_in, const int* in_sizes, int n_in,
                              void* d_out, int out_size) {
    const float* x  = (const float*)d_in[0];   // [8192, 512]
    const float* gw = (const float*)d_in[1];   // [512, 32]
    const float* gb = (const float*)d_in[2];   // [32]
    const float* ew = (const float*)d_in[3];   // [32, 512, 512]
    float* out = (float*)d_out;                // [8192, 512]

    cudaFuncSetAttribute(prep_gate_kernel,
                         cudaFuncAttributeMaxDynamicSharedMemorySize, PRE_SMEM);
    cudaFuncSetAttribute(moe_main_kernel,
                         cudaFuncAttributeMaxDynamicSharedMemorySize, MAIN_SMEM);

    prep_gate_kernel<<<576, 256, PRE_SMEM>>>(ew, x, gw, gb);

    dim3 grid(4, 64);
    moe_main_kernel<<<grid, 128, MAIN_SMEM>>>(x, out);
}